// round 6
// baseline (speedup 1.0000x reference)
#include <cuda_runtime.h>
#include <float.h>
#include <math.h>

// Problem constants
#define Bn   4
#define Qn   4
#define Fn   20
#define OBJn 20
#define Dn   4096
#define Mn   1000
#define ROWn (OBJn * Dn)          // 81920 floats per (frame|mem) row
#define BFn  (Bn * Fn)            // 80
#define KSPLIT 16
#define KPER   (Dn / KSPLIT)      // 256
#define MPAD 2048

static const size_t RPN = (size_t)Qn * Bn * Fn * ROWn;   // 26,214,400 elems per big output

// ---------------- device scratch (static allocation; no cudaMalloc allowed) ----------
__device__ float g_rmaxn[BFn * Dn];              // 1.3 MB: normalized maxpooled R rows
__device__ float g_invnorm[BFn * OBJn];          // per-region inverse norms
__device__ float g_partial[KSPLIT * BFn * MPAD]; // 10.5 MB: k-split raw-dot partials
__device__ float g_psq[KSPLIT * MPAD];           // k-split partial sumsq of pooled mem rows
__device__ int   g_sim[2 * BFn];                 // sim1 (0..79), sim2 (80..159)
__device__ int   g_high[16], g_low[16];          // indexed by b*4+q

// ---------------- helpers ----------------
__device__ __forceinline__ float block_reduce_sum(float v) {
    __shared__ float sh[32];
    __shared__ float res;
    int lane = threadIdx.x & 31, w = threadIdx.x >> 5;
#pragma unroll
    for (int o = 16; o; o >>= 1) v += __shfl_down_sync(0xffffffffu, v, o);
    __syncthreads();
    if (!lane) sh[w] = v;
    __syncthreads();
    if (w == 0) {
        float x = (lane < (int)(blockDim.x >> 5)) ? sh[lane] : 0.f;
#pragma unroll
        for (int o = 16; o; o >>= 1) x += __shfl_down_sync(0xffffffffu, x, o);
        if (!lane) res = x;
    }
    __syncthreads();
    return res;
}

__device__ __forceinline__ float4 fmax4(float4 a, float4 b) {
    a.x = fmaxf(a.x, b.x); a.y = fmaxf(a.y, b.y);
    a.z = fmaxf(a.z, b.z); a.w = fmaxf(a.w, b.w);
    return a;
}

// ---------------- K_sel: frame selection from qr/rnd only ----------------
__global__ void k_sel(const float* __restrict__ qr, const int* __restrict__ rnd) {
    int t = threadIdx.x;
    if (t >= 16) return;
    int b = t >> 2, q = t & 3;                // t = b*4 + q
    const float* w = qr + (b * Qn + q) * Fn;
    int hi = 0; float hv = w[0];
    for (int f = 1; f < Fn; f++) if (w[f] > hv) { hv = w[f]; hi = f; }
    int rr = rnd[b * Qn + q];
    int lo = 0;
    for (int i = 0; i < Fn; i++) {
        int rank = 0;
        for (int j = 0; j < Fn; j++)
            rank += (w[j] < w[i]) || (w[j] == w[i] && j < i);
        if (rank == rr) { lo = i; break; }
    }
    g_high[t] = hi; g_low[t] = lo;
}

// ---------------- K2: per-(b,f) region norms + maxpool + l2norm ----------------
__global__ __launch_bounds__(256) void k_rstats(const float* __restrict__ inp) {
    int bf = blockIdx.x;
    const float* base = inp + (size_t)bf * ROWn;
    float4 mx[4];
#pragma unroll
    for (int i = 0; i < 4; i++) mx[i] = make_float4(-FLT_MAX, -FLT_MAX, -FLT_MAX, -FLT_MAX);
    for (int o = 0; o < OBJn; o++) {
        float4 x[4];
        const float4* p = (const float4*)(base + (size_t)o * Dn);
        float s = 0.f;
#pragma unroll
        for (int i = 0; i < 4; i++) {
            x[i] = p[threadIdx.x + i * 256];
            s += x[i].x * x[i].x + x[i].y * x[i].y + x[i].z * x[i].z + x[i].w * x[i].w;
        }
        s = block_reduce_sum(s);
        float inv = 1.f / fmaxf(sqrtf(s), 1e-12f);
        if (threadIdx.x == 0) g_invnorm[bf * OBJn + o] = inv;
#pragma unroll
        for (int i = 0; i < 4; i++) {
            float4 v = x[i];
            v.x *= inv; v.y *= inv; v.z *= inv; v.w *= inv;
            mx[i] = fmax4(mx[i], v);
        }
    }
    float s2 = 0.f;
#pragma unroll
    for (int i = 0; i < 4; i++)
        s2 += mx[i].x * mx[i].x + mx[i].y * mx[i].y + mx[i].z * mx[i].z + mx[i].w * mx[i].w;
    s2 = block_reduce_sum(s2);
    float inv2 = 1.f / fmaxf(sqrtf(s2), 1e-12f);
    float4* out = (float4*)(g_rmaxn + (size_t)bf * Dn);
#pragma unroll
    for (int i = 0; i < 4; i++) {
        float4 v = mx[i];
        v.x *= inv2; v.y *= inv2; v.z *= inv2; v.w *= inv2;
        out[threadIdx.x + i * 256] = v;
    }
}

// ---------------- K3: FUSED maxpool + GEMM, double-buffered ----------------
// grid (32 m-tiles of 64, 16 k-splits of 256), 256 threads.
// A (80 x 256 slice) resident in smem; B (pooled mem) register-prefetched one
// chunk ahead and ping-ponged through smem -> DRAM stream overlaps FMA loop.
#define SM_AS   (80 * 257)
#define SM_BS   (64 * 33)
#define SM_TOT  ((SM_AS + 2 * SM_BS) * 4)     // 96.8 KB (GB300: 228 KB/SM)

__global__ __launch_bounds__(256) void k_gfused(const float* __restrict__ mem1,
                                                const float* __restrict__ mem2) {
    extern __shared__ float sm[];
    float* As = sm;                         // [80][257]
    float* Bs = sm + SM_AS;                 // [2][64][33]

    int tid = threadIdx.x;
    int m0 = blockIdx.x * 64;
    int ks = blockIdx.y;
    int kbase = ks * KPER;

    // resident A slice: As[r][k] = g_rmaxn[r][kbase+k]  (coalesced, conflict-free)
    for (int idx = tid; idx < 80 * KPER; idx += 256) {
        int r = idx >> 8, k = idx & 255;
        As[r * 257 + k] = g_rmaxn[(size_t)r * Dn + kbase + k];
    }

    // B mapping: thread owns rows (lm, lm+32), 4-float group kq
    int lm = tid >> 3;            // 0..31
    int kq = tid & 7;             // 0..7
    int mgA = m0 + lm, mgB = m0 + lm + 32;
    bool vA = (mgA < 2 * Mn), vB = (mgB < 2 * Mn);
    const float4* pA4 = (const float4*)(vA ? ((mgA < Mn) ? mem1 + (size_t)mgA * ROWn
                                                         : mem2 + (size_t)(mgA - Mn) * ROWn)
                                           : mem1);
    const float4* pB4 = (const float4*)(vB ? ((mgB < Mn) ? mem1 + (size_t)mgB * ROWn
                                                         : mem2 + (size_t)(mgB - Mn) * ROWn)
                                           : mem1);
    int f4base = (kbase >> 2) + kq;

    float sqA = 0.f, sqB = 0.f;

    // pooled-chunk producer: 20 regions in 4 groups of 5 (loads batched for MLP)
#define POOL(KC, OA, OB)                                                       \
    {                                                                          \
        int f4 = f4base + (KC) * 8;                                            \
        OA = make_float4(-FLT_MAX, -FLT_MAX, -FLT_MAX, -FLT_MAX);              \
        OB = OA;                                                               \
        _Pragma("unroll")                                                      \
        for (int g = 0; g < 4; g++) {                                          \
            float4 ta[5], tb[5];                                               \
            _Pragma("unroll")                                                  \
            for (int j = 0; j < 5; j++) {                                      \
                ta[j] = __ldg(pA4 + (size_t)(g * 5 + j) * (Dn / 4) + f4);      \
                tb[j] = __ldg(pB4 + (size_t)(g * 5 + j) * (Dn / 4) + f4);      \
            }                                                                  \
            _Pragma("unroll")                                                  \
            for (int j = 0; j < 5; j++) {                                      \
                OA = fmax4(OA, ta[j]); OB = fmax4(OB, tb[j]);                  \
            }                                                                  \
        }                                                                      \
        if (!vA) OA = make_float4(0.f, 0.f, 0.f, 0.f);                         \
        if (!vB) OB = make_float4(0.f, 0.f, 0.f, 0.f);                         \
        sqA += OA.x * OA.x + OA.y * OA.y + OA.z * OA.z + OA.w * OA.w;          \
        sqB += OB.x * OB.x + OB.y * OB.y + OB.z * OB.z + OB.w * OB.w;          \
    }

#define BSTORE(BUF, VA, VB)                                                    \
    {                                                                          \
        float* p = Bs + (BUF) * SM_BS + lm * 33 + kq * 4;                      \
        p[0] = VA.x; p[1] = VA.y; p[2] = VA.z; p[3] = VA.w;                    \
        p += 32 * 33;                                                          \
        p[0] = VB.x; p[1] = VB.y; p[2] = VB.z; p[3] = VB.w;                    \
    }

    // compute mapping: 5x4 micro-tile
    int tx = tid & 15, ty = tid >> 4;
    float acc[5][4];
#pragma unroll
    for (int i = 0; i < 5; i++)
#pragma unroll
        for (int j = 0; j < 4; j++) acc[i][j] = 0.f;

    // prologue: pool chunk 0, publish to buffer 0 (also covers As visibility)
    float4 a4, b4;
    POOL(0, a4, b4);
    __syncthreads();              // As writes done before anyone reads
    BSTORE(0, a4, b4);
    __syncthreads();

    const int NCH = KPER / 32;    // 8
    for (int kc = 0; kc < NCH; kc++) {
        int cur = kc & 1;
        float4 na4, nb4;
        if (kc + 1 < NCH) POOL(kc + 1, na4, nb4);     // loads in flight during FMAs
        const float* ap = As + kc * 32;
        const float* bp = Bs + cur * SM_BS;
#pragma unroll
        for (int kk = 0; kk < 32; kk++) {
            float a[5], b[4];
#pragma unroll
            for (int i = 0; i < 5; i++) a[i] = ap[(ty * 5 + i) * 257 + kk];
#pragma unroll
            for (int j = 0; j < 4; j++) b[j] = bp[(tx * 4 + j) * 33 + kk];
#pragma unroll
            for (int i = 0; i < 5; i++)
#pragma unroll
                for (int j = 0; j < 4; j++) acc[i][j] = fmaf(a[i], b[j], acc[i][j]);
        }
        if (kc + 1 < NCH) BSTORE(cur ^ 1, na4, nb4);
        __syncthreads();
    }

    // write raw-dot partials
    float* dst = g_partial + (size_t)ks * BFn * MPAD;
#pragma unroll
    for (int i = 0; i < 5; i++)
#pragma unroll
        for (int j = 0; j < 4; j++)
            dst[(ty * 5 + i) * MPAD + m0 + tx * 4 + j] = acc[i][j];

    // reduce sumsq across the 8 kq lanes of each row
#pragma unroll
    for (int o = 4; o; o >>= 1) {
        sqA += __shfl_down_sync(0xffffffffu, sqA, o, 8);
        sqB += __shfl_down_sync(0xffffffffu, sqB, o, 8);
    }
    if (kq == 0) {
        g_psq[ks * MPAD + m0 + lm]      = sqA;
        g_psq[ks * MPAD + m0 + lm + 32] = sqB;
    }
#undef POOL
#undef BSTORE
}

// ---------------- K3b: reduce partials, normalize, argmax per mem half ----------------
__global__ __launch_bounds__(512) void k_argmax() {
    int r = blockIdx.x;
    int tid = threadIdx.x;
    float bv[2] = {-FLT_MAX, -FLT_MAX};
    int   bm[2] = {0, 0};
    for (int m = tid; m < 2 * Mn; m += 512) {
        float s = 0.f, n = 0.f;
#pragma unroll
        for (int ks = 0; ks < KSPLIT; ks++) {
            s += g_partial[(size_t)ks * BFn * MPAD + (size_t)r * MPAD + m];
            n += g_psq[ks * MPAD + m];
        }
        float sc = s * (1.f / fmaxf(sqrtf(n), 1e-12f));
        int h = (m >= Mn);
        int mm = h ? m - Mn : m;
        if (sc > bv[h] || (sc == bv[h] && mm < bm[h])) { bv[h] = sc; bm[h] = mm; }
    }
    __shared__ float sv[2][512];
    __shared__ int   sm2[2][512];
    sv[0][tid] = bv[0]; sm2[0][tid] = bm[0];
    sv[1][tid] = bv[1]; sm2[1][tid] = bm[1];
    __syncthreads();
    for (int st = 256; st; st >>= 1) {
        if (tid < st) {
#pragma unroll
            for (int h = 0; h < 2; h++) {
                float ov = sv[h][tid + st]; int om = sm2[h][tid + st];
                if (ov > sv[h][tid] || (ov == sv[h][tid] && om < sm2[h][tid])) {
                    sv[h][tid] = ov; sm2[h][tid] = om;
                }
            }
        }
        __syncthreads();
    }
    if (tid == 0) { g_sim[r] = sm2[0][0]; g_sim[BFn + r] = sm2[1][0]; }
}

// ---------------- K5a: bulk fill ----------------
__global__ __launch_bounds__(256) void k_fill(const float* __restrict__ inp,
                                              float* __restrict__ out) {
    int bf = blockIdx.x;
    int b = bf / Fn, f = bf % Fn;
    int lows[4], highs[4];
#pragma unroll
    for (int q = 0; q < 4; q++) { lows[q] = g_low[b * 4 + q]; highs[q] = g_high[b * 4 + q]; }
    const float4* src = (const float4*)(inp + (size_t)bf * ROWn);
    float4* o4 = (float4*)out;
    const float* invp = g_invnorm + bf * OBJn;
    const size_t rpn4 = RPN / 4;
    int e4base = blockIdx.y * 1280;
#pragma unroll
    for (int i = 0; i < 5; i++) {
        int e4 = e4base + threadIdx.x + i * 256;
        int oo = e4 >> 10;
        float inv = invp[oo];
        float4 v = src[e4];
        v.x *= inv; v.y *= inv; v.z *= inv; v.w *= inv;
#pragma unroll
        for (int q = 0; q < 4; q++) {
            size_t ob = ((size_t)((q * Bn + b) * Fn + f)) * (ROWn / 4) + e4;
            if (f != lows[q])  o4[ob] = v;
            if (f != highs[q]) o4[rpn4 + ob] = v;
        }
    }
}

// ---------------- K5b: replaced rows + sim outputs ----------------
__global__ __launch_bounds__(256) void k_replace(const float* __restrict__ mem1,
                                                 const float* __restrict__ mem2,
                                                 float* __restrict__ out,
                                                 long long out_size) {
    int t = blockIdx.x;
    if (t == 32) {
        if (blockIdx.y == 0 && threadIdx.x < 16) {
            int bq = threadIdx.x;
            int b = bq >> 2, q = bq & 3;
            long long rpn2 = (long long)(2 * RPN);
            if (out_size >= rpn2 + 32) {
                out[(size_t)rpn2 + (q * Bn + b)]      =
                    (float)g_sim[BFn + b * Fn + g_high[bq]];   // high_sim
                out[(size_t)rpn2 + 16 + (q * Bn + b)] =
                    (float)g_sim[b * Fn + g_low[bq]];          // low_sim
            }
        }
        return;
    }
    int which = t & 1;
    int bq = t >> 1;
    int b = bq >> 2, q = bq & 3;
    int f, row;
    const float* src;
    int lo = g_low[bq];
    if (which == 0) { f = lo;         row = g_sim[b * Fn + lo];       src = mem1; }
    else            { f = g_high[bq]; row = g_sim[BFn + b * Fn + lo]; src = mem2; }
    const float4* s4 = (const float4*)(src + (size_t)row * ROWn);
    float4* d4 = (float4*)(out + (size_t)which * RPN +
                           ((size_t)((q * Bn + b) * Fn + f)) * ROWn);
    int base = blockIdx.y * 2560;
#pragma unroll
    for (int i = 0; i < 10; i++) {
        int e4 = base + threadIdx.x + i * 256;
        d4[e4] = s4[e4];
    }
}

// ---------------- launch (single stream) ----------------
extern "C" void kernel_launch(void* const* d_in, const int* in_sizes, int n_in,
                              void* d_out, int out_size) {
    const float* qr   = (const float*)d_in[0];   // [4,4,20]
    const float* inp  = (const float*)d_in[1];   // [4,20,20,4096]
    const float* mem1 = (const float*)d_in[2];   // [1000,81920]
    const float* mem2 = (const float*)d_in[3];   // [1000,81920]
    const int*   rnd  = (const int*)d_in[4];     // [4,4,1]
    float* out = (float*)d_out;

    // opt into 96.8 KB dynamic smem (idempotent; not a stream op, capture-safe)
    cudaFuncSetAttribute((const void*)k_gfused,
                         cudaFuncAttributeMaxDynamicSharedMemorySize, SM_TOT);

    k_sel<<<1, 32>>>(qr, rnd);
    k_rstats<<<BFn, 256>>>(inp);
    k_gfused<<<dim3(32, KSPLIT), 256, SM_TOT>>>(mem1, mem2);
    k_argmax<<<BFn, 512>>>();
    k_fill<<<dim3(BFn, 16), 256>>>(inp, out);
    k_replace<<<dim3(33, 8), 256>>>(mem1, mem2, out, (long long)out_size);
}

// round 7
// speedup vs baseline: 1.1802x; 1.1802x over previous
#include <cuda_runtime.h>
#include <float.h>
#include <math.h>

// Problem constants
#define Bn   4
#define Qn   4
#define Fn   20
#define OBJn 20
#define Dn   4096
#define Mn   1000
#define ROWn (OBJn * Dn)          // 81920 floats per (frame|mem) row
#define BFn  (Bn * Fn)            // 80
#define KSPLIT 8
#define MPAD 2048

static const size_t RPN = (size_t)Qn * Bn * Fn * ROWn;   // 26,214,400 elems per big output

// ---------------- device scratch ----------------
__device__ float g_mem_mp[2 * Mn * Dn];          // 32.8 MB: normalized maxpooled mem rows
__device__ float g_rmaxn[BFn * Dn];              // normalized maxpooled R rows
__device__ float g_invnorm[BFn * OBJn];          // per-region inverse norms
__device__ float g_partial[KSPLIT * BFn * MPAD]; // k-split partial dots
__device__ int   g_sim[2 * BFn];                 // sim1 (0..79), sim2 (80..159)
__device__ int   g_high[16], g_low[16];          // indexed by b*4+q

// ---------------- helpers ----------------
__device__ __forceinline__ float block_reduce_sum(float v) {
    __shared__ float sh[32];
    __shared__ float res;
    int lane = threadIdx.x & 31, w = threadIdx.x >> 5;
#pragma unroll
    for (int o = 16; o; o >>= 1) v += __shfl_down_sync(0xffffffffu, v, o);
    __syncthreads();
    if (!lane) sh[w] = v;
    __syncthreads();
    if (w == 0) {
        float x = (lane < (int)(blockDim.x >> 5)) ? sh[lane] : 0.f;
#pragma unroll
        for (int o = 16; o; o >>= 1) x += __shfl_down_sync(0xffffffffu, x, o);
        if (!lane) res = x;
    }
    __syncthreads();
    return res;
}

__device__ __forceinline__ float4 fmax4(float4 a, float4 b) {
    a.x = fmaxf(a.x, b.x); a.y = fmaxf(a.y, b.y);
    a.z = fmaxf(a.z, b.z); a.w = fmaxf(a.w, b.w);
    return a;
}

// ---------------- K_prep: heterogeneous grid -----------------------------------------
// blocks [0,2000): mem max-pool+norm   [2000,2080): R stats   2080: frame selection
__global__ __launch_bounds__(256) void k_prep(const float* __restrict__ mem1,
                                              const float* __restrict__ mem2,
                                              const float* __restrict__ inp,
                                              const float* __restrict__ qr,
                                              const int* __restrict__ rnd) {
    int blk = blockIdx.x;
    if (blk < 2 * Mn) {
        // ---- mem_mp (proven 100us @ 86% DRAM) ----
        const float* src = (blk >= Mn) ? (mem2 + (size_t)(blk - Mn) * ROWn)
                                       : (mem1 + (size_t)blk * ROWn);
        float4 mx[4];
#pragma unroll
        for (int i = 0; i < 4; i++) mx[i] = make_float4(-FLT_MAX, -FLT_MAX, -FLT_MAX, -FLT_MAX);
        for (int o = 0; o < OBJn; o++) {
            const float4* p = (const float4*)(src + (size_t)o * Dn);
#pragma unroll
            for (int i = 0; i < 4; i++) mx[i] = fmax4(mx[i], p[threadIdx.x + i * 256]);
        }
        float s = 0.f;
#pragma unroll
        for (int i = 0; i < 4; i++)
            s += mx[i].x * mx[i].x + mx[i].y * mx[i].y + mx[i].z * mx[i].z + mx[i].w * mx[i].w;
        s = block_reduce_sum(s);
        float inv = 1.f / fmaxf(sqrtf(s), 1e-12f);
        float4* out = (float4*)(g_mem_mp + (size_t)blk * Dn);
#pragma unroll
        for (int i = 0; i < 4; i++) {
            float4 v = mx[i];
            v.x *= inv; v.y *= inv; v.z *= inv; v.w *= inv;
            out[threadIdx.x + i * 256] = v;
        }
    } else if (blk < 2 * Mn + BFn) {
        // ---- rstats ----
        int bf = blk - 2 * Mn;
        const float* base = inp + (size_t)bf * ROWn;
        float4 mx[4];
#pragma unroll
        for (int i = 0; i < 4; i++) mx[i] = make_float4(-FLT_MAX, -FLT_MAX, -FLT_MAX, -FLT_MAX);
        for (int o = 0; o < OBJn; o++) {
            float4 x[4];
            const float4* p = (const float4*)(base + (size_t)o * Dn);
            float s = 0.f;
#pragma unroll
            for (int i = 0; i < 4; i++) {
                x[i] = p[threadIdx.x + i * 256];
                s += x[i].x * x[i].x + x[i].y * x[i].y + x[i].z * x[i].z + x[i].w * x[i].w;
            }
            s = block_reduce_sum(s);
            float inv = 1.f / fmaxf(sqrtf(s), 1e-12f);
            if (threadIdx.x == 0) g_invnorm[bf * OBJn + o] = inv;
#pragma unroll
            for (int i = 0; i < 4; i++) {
                float4 v = x[i];
                v.x *= inv; v.y *= inv; v.z *= inv; v.w *= inv;
                mx[i] = fmax4(mx[i], v);
            }
        }
        float s2 = 0.f;
#pragma unroll
        for (int i = 0; i < 4; i++)
            s2 += mx[i].x * mx[i].x + mx[i].y * mx[i].y + mx[i].z * mx[i].z + mx[i].w * mx[i].w;
        s2 = block_reduce_sum(s2);
        float inv2 = 1.f / fmaxf(sqrtf(s2), 1e-12f);
        float4* outp = (float4*)(g_rmaxn + (size_t)bf * Dn);
#pragma unroll
        for (int i = 0; i < 4; i++) {
            float4 v = mx[i];
            v.x *= inv2; v.y *= inv2; v.z *= inv2; v.w *= inv2;
            outp[threadIdx.x + i * 256] = v;
        }
    } else {
        // ---- frame selection ----
        int t = threadIdx.x;
        if (t < 16) {
            int b = t >> 2, q = t & 3;
            const float* w = qr + (b * Qn + q) * Fn;
            int hi = 0; float hv = w[0];
            for (int f = 1; f < Fn; f++) if (w[f] > hv) { hv = w[f]; hi = f; }
            int rr = rnd[b * Qn + q];
            int lo = 0;
            for (int i = 0; i < Fn; i++) {
                int rank = 0;
                for (int j = 0; j < Fn; j++)
                    rank += (w[j] < w[i]) || (w[j] == w[i] && j < i);
                if (rank == rr) { lo = i; break; }
            }
            g_high[t] = hi; g_low[t] = lo;
        }
    }
}

// ---------------- K_main: heterogeneous grid -----------------------------------------
// blocks [0,256): GEMM tiles (FMA-bound)   [256,1536): bulk fill (DRAM-bound)
// No data dependence between the halves; they co-occupy the chip so the GEMM's
// 35us FMA floor hides under fill's DRAM stream.
__global__ __launch_bounds__(256) void k_main(const float* __restrict__ inp,
                                              float* __restrict__ out) {
    __shared__ float As[80][33];
    __shared__ float Bs[64][33];
    int blk = blockIdx.x;
    int tid = threadIdx.x;

    if (blk < 256) {
        // ---- GEMM (identical to proven 35us round-3 kernel) ----
        int tx = tid & 15, ty = tid >> 4;     // tx: m (16x4=64), ty: r (16x5=80)
        int m0 = (blk & 31) * 64;
        int ks = blk >> 5;
        int kbase = ks * 512;
        float acc[5][4];
#pragma unroll
        for (int i = 0; i < 5; i++)
#pragma unroll
            for (int j = 0; j < 4; j++) acc[i][j] = 0.f;

        for (int kc = 0; kc < 16; kc++) {
            int k0 = kbase + kc * 32;
            __syncthreads();
#pragma unroll
            for (int idx = tid; idx < 80 * 32; idx += 256) {
                int r = idx >> 5, kk = idx & 31;
                As[r][kk] = g_rmaxn[(size_t)r * Dn + k0 + kk];
            }
#pragma unroll
            for (int idx = tid; idx < 64 * 32; idx += 256) {
                int m = idx >> 5, kk = idx & 31;
                int mg = m0 + m;
                Bs[m][kk] = (mg < 2 * Mn) ? g_mem_mp[(size_t)mg * Dn + k0 + kk] : 0.f;
            }
            __syncthreads();
#pragma unroll
            for (int kk = 0; kk < 32; kk++) {
                float a[5], b[4];
#pragma unroll
                for (int i = 0; i < 5; i++) a[i] = As[ty * 5 + i][kk];
#pragma unroll
                for (int j = 0; j < 4; j++) b[j] = Bs[tx * 4 + j][kk];
#pragma unroll
                for (int i = 0; i < 5; i++)
#pragma unroll
                    for (int j = 0; j < 4; j++) acc[i][j] = fmaf(a[i], b[j], acc[i][j]);
            }
        }
        float* dst = g_partial + (size_t)ks * BFn * MPAD;
#pragma unroll
        for (int i = 0; i < 5; i++)
#pragma unroll
            for (int j = 0; j < 4; j++)
                dst[(ty * 5 + i) * MPAD + m0 + tx * 4 + j] = acc[i][j];
    } else {
        // ---- bulk fill (identical math to proven 38.7us round-3 kernel) ----
        int fb = blk - 256;                   // 0..1279
        int bf = fb % BFn;
        int ch = fb / BFn;                    // 0..15
        int b = bf / Fn, f = bf % Fn;
        int lows[4], highs[4];
#pragma unroll
        for (int q = 0; q < 4; q++) { lows[q] = g_low[b * 4 + q]; highs[q] = g_high[b * 4 + q]; }
        const float4* src = (const float4*)(inp + (size_t)bf * ROWn);
        float4* o4 = (float4*)out;
        const float* invp = g_invnorm + bf * OBJn;
        const size_t rpn4 = RPN / 4;
        int e4base = ch * 1280;
#pragma unroll
        for (int i = 0; i < 5; i++) {
            int e4 = e4base + tid + i * 256;
            int oo = e4 >> 10;                 // region (1024 float4 per region)
            float inv = invp[oo];
            float4 v = src[e4];
            v.x *= inv; v.y *= inv; v.z *= inv; v.w *= inv;
#pragma unroll
            for (int q = 0; q < 4; q++) {
                size_t ob = ((size_t)((q * Bn + b) * Fn + f)) * (ROWn / 4) + e4;
                if (f != lows[q])  o4[ob] = v;          // Rp copy
                if (f != highs[q]) o4[rpn4 + ob] = v;   // Rn copy
            }
        }
    }
}

// ---------------- K_argmax: one block per (row, mem-half) ----------------------------
__global__ __launch_bounds__(512) void k_argmax() {
    int r = blockIdx.x >> 1;
    int h = blockIdx.x & 1;
    int tid = threadIdx.x;
    float bv = -FLT_MAX;
    int   bm = 0;
    for (int m = tid; m < Mn; m += 512) {
        int mg = h * Mn + m;
        float s = 0.f;
#pragma unroll
        for (int ks = 0; ks < KSPLIT; ks++)
            s += g_partial[(size_t)ks * BFn * MPAD + (size_t)r * MPAD + mg];
        if (s > bv || (s == bv && m < bm)) { bv = s; bm = m; }
    }
    __shared__ float sv[512];
    __shared__ int   sm2[512];
    sv[tid] = bv; sm2[tid] = bm;
    __syncthreads();
    for (int st = 256; st; st >>= 1) {
        if (tid < st) {
            float ov = sv[tid + st]; int om = sm2[tid + st];
            if (ov > sv[tid] || (ov == sv[tid] && om < sm2[tid])) {
                sv[tid] = ov; sm2[tid] = om;
            }
        }
        __syncthreads();
    }
    if (tid == 0) g_sim[h * BFn + r] = sm2[0];
}

// ---------------- K_replace: replaced rows + sim outputs -----------------------------
__global__ __launch_bounds__(256) void k_replace(const float* __restrict__ mem1,
                                                 const float* __restrict__ mem2,
                                                 float* __restrict__ out,
                                                 long long out_size) {
    int t = blockIdx.x;
    if (t == 32) {
        if (blockIdx.y == 0 && threadIdx.x < 16) {
            int bq = threadIdx.x;
            int b = bq >> 2, q = bq & 3;
            long long rpn2 = (long long)(2 * RPN);
            if (out_size >= rpn2 + 32) {
                out[(size_t)rpn2 + (q * Bn + b)]      =
                    (float)g_sim[BFn + b * Fn + g_high[bq]];   // high_sim
                out[(size_t)rpn2 + 16 + (q * Bn + b)] =
                    (float)g_sim[b * Fn + g_low[bq]];          // low_sim
            }
        }
        return;
    }
    int which = t & 1;         // 0: Rp/low/mem1   1: Rn/high/mem2
    int bq = t >> 1;
    int b = bq >> 2, q = bq & 3;
    int f, row;
    const float* src;
    int lo = g_low[bq];
    if (which == 0) { f = lo;         row = g_sim[b * Fn + lo];       src = mem1; }
    else            { f = g_high[bq]; row = g_sim[BFn + b * Fn + lo]; src = mem2; }
    const float4* s4 = (const float4*)(src + (size_t)row * ROWn);
    float4* d4 = (float4*)(out + (size_t)which * RPN +
                           ((size_t)((q * Bn + b) * Fn + f)) * ROWn);
    int base = blockIdx.y * 2560;
#pragma unroll
    for (int i = 0; i < 10; i++) {
        int e4 = base + threadIdx.x + i * 256;
        d4[e4] = s4[e4];
    }
}

// ---------------- launch ----------------
extern "C" void kernel_launch(void* const* d_in, const int* in_sizes, int n_in,
                              void* d_out, int out_size) {
    const float* qr   = (const float*)d_in[0];   // [4,4,20]
    const float* inp  = (const float*)d_in[1];   // [4,20,20,4096]
    const float* mem1 = (const float*)d_in[2];   // [1000,81920]
    const float* mem2 = (const float*)d_in[3];   // [1000,81920]
    const int*   rnd  = (const int*)d_in[4];     // [4,4,1]
    float* out = (float*)d_out;

    k_prep<<<2 * Mn + BFn + 1, 256>>>(mem1, mem2, inp, qr, rnd);
    k_main<<<256 + BFn * 16, 256>>>(inp, out);
    k_argmax<<<2 * BFn, 512>>>();
    k_replace<<<dim3(33, 8), 256>>>(mem1, mem2, out, (long long)out_size);
}